// round 14
// baseline (speedup 1.0000x reference)
#include <cuda_runtime.h>
#include <cuda_fp16.h>
#include <cstdint>

#define GG 512            // B*T graphs
#define NN 500            // nodes
#define NP 512            // padded node count (MMA K/M)
#define FIN 96
#define HID 64
#define OUTF 96
#define ROWS (GG*NN)      // 256000
#define BN_EPS 1e-5f

// ---------------- scratch (device globals; no allocation allowed) ----------------
// g_t16 has 16 rows of slack: padded-K B-reads (rows 500..511) land there.
// Device globals are zero-initialized and the slack is never written -> reads 0.
__device__ __half2 g_t16[((long)ROWS + 16)*HID/2]; // GEMM output / SpMM input (fp16)
// a_hat in fragment-major layout: word @ (((tau*16 + c)*2 + s)*128 + lane*4 + reg)
__device__ uint32_t g_afrag[32*16*2*128];          // 131072 words = 512KB
__device__ float g_s[(long)ROWS*HID];    // SpMM output
__device__ float g_h[(long)ROWS*HID];    // layer activations (residual chain)
__device__ float g_r[(long)ROWS*HID];    // layer-0 residual (x @ w_r0 + b_r0)
__device__ float g_dinv[NN];
__device__ float g_sum[HID];
__device__ float g_sumsq[HID];
__device__ float g_scale[HID];
__device__ float g_shift[HID];

// ---------------- prep 1: degrees -> dinv ----------------
__global__ void prep_deg(const float* __restrict__ adj) {
    int m = blockIdx.x;
    int tid = threadIdx.x;
    float sum = 0.f;
    for (int n = tid; n < NN; n += blockDim.x) sum += adj[m*NN + n];
    __shared__ float ssum[4];
    #pragma unroll
    for (int o = 16; o; o >>= 1) sum += __shfl_down_sync(0xFFFFFFFFu, sum, o);
    int w = tid >> 5;
    if ((tid & 31) == 0) ssum[w] = sum;
    __syncthreads();
    if (tid == 0)
        g_dinv[m] = rsqrtf(1.f + ssum[0] + ssum[1] + ssum[2] + ssum[3]);
    if (blockIdx.x == 0 && tid < HID) { g_sum[tid] = 0.f; g_sumsq[tid] = 0.f; }
}

// ---------------- prep 2: build fragment-major fp16 a_hat directly ----------------
__device__ __forceinline__ float ahat_val(const float* adj, const float* dinv, int m, int n) {
    if (m >= NN || n >= NN) return 0.f;
    float dm = dinv[m];
    return (n == m) ? dm * dm : adj[m*NN + n] * dm * dinv[n];
}

__global__ __launch_bounds__(256) void prep_fill_frag(const float* __restrict__ adj) {
    __shared__ float sdinv[NN];
    int tid = threadIdx.x;
    for (int i = tid; i < NN; i += 256) sdinv[i] = g_dinv[i];
    __syncthreads();
    int idx = blockIdx.x * 256 + tid;           // 0 .. 131071
    int reg = idx & 3;
    int l   = (idx >> 2) & 31;
    int s   = (idx >> 7) & 1;
    int c   = (idx >> 8) & 15;
    int tau = idx >> 12;
    int g = l >> 2, t4 = l & 3;
    int row = tau * 16 + g + (reg & 1) * 8;
    int kp  = c * 16 + s * 8 + t4 + (reg >> 1) * 4;
    __half2 v = __floats2half2_rn(ahat_val(adj, sdinv, row, 2*kp),
                                  ahat_val(adj, sdinv, row, 2*kp + 1));
    g_afrag[idx] = *(uint32_t*)&v;
}

// ---------------- fp16 MMA helpers ----------------
__device__ __forceinline__ uint32_t h2u(__half2 h) { return *(uint32_t*)&h; }

__device__ __forceinline__ void f16_split2(float a, float b, uint32_t& hi, uint32_t& lo) {
    __half2 h = __floats2half2_rn(a, b);
    float2 back = __half22float2(h);
    __half2 l = __floats2half2_rn(a - back.x, b - back.y);
    hi = h2u(h); lo = h2u(l);
}

__device__ __forceinline__ void mma_f16(float* c, const uint32_t* a, const uint32_t* b) {
    asm volatile(
        "mma.sync.aligned.m16n8k16.row.col.f32.f16.f16.f32 "
        "{%0,%1,%2,%3}, {%4,%5,%6,%7}, {%8,%9}, {%0,%1,%2,%3};\n"
        : "+f"(c[0]), "+f"(c[1]), "+f"(c[2]), "+f"(c[3])
        : "r"(a[0]), "r"(a[1]), "r"(a[2]), "r"(a[3]), "r"(b[0]), "r"(b[1]));
}

// ---------------- SpMM as batched dense MMA + fused BN stats (v4) ----------------
// grid (2, GG): M=256 rows per block -> each B fragment feeds 4 MMAs (was 2),
// halving L1 wavefronts per MMA (measured L1-pipe bound at 68.6%).
// A fragments straight from g_afrag (L1-resident). B staging double-buffered.
__global__ __launch_bounds__(256) void spmm_mma(
    const __half2* __restrict__ T2, float* __restrict__ S)
{
    __shared__ uint32_t Bs[2][16][72];
    __shared__ float ssum[8][32], ssq[8][32];

    const int tid = threadIdx.x;
    const int wid = tid >> 5;
    const int lane = tid & 31;
    const int g  = lane >> 2;
    const int t4 = lane & 3;
    const int warp_m = wid >> 1;       // 0..3, each covers 64 rows (4 m-tiles)
    const int warp_n = wid & 1;

    const int gph = blockIdx.y;
    const int rt = blockIdx.x;         // 0..1 (256-row tile)
    const __half* Tg = (const __half*)T2 + (long)gph * NN * HID;
    float* Sg = S + (long)gph * NN * HID;

    const int bkp = tid >> 3;          // 0..15 (staging kpair; lower 128 threads)
    const int bcq = tid & 7;           // 0..7  (8-channel group)

    auto stageB = [&](int c, uint32_t (*B)[72]) {
        long k = c * 32 + 2 * bkp;
        uint4 lo = *(const uint4*)(Tg + k * HID + bcq * 8);
        uint4 hi = *(const uint4*)(Tg + (k + 1) * HID + bcq * 8);
        const __half2* l2 = (const __half2*)&lo;
        const __half2* h2 = (const __half2*)&hi;
        uint32_t w[8];
        #pragma unroll
        for (int j = 0; j < 4; j++) {
            w[2*j]   = h2u(__lows2half2(l2[j], h2[j]));
            w[2*j+1] = h2u(__highs2half2(l2[j], h2[j]));
        }
        *(uint4*)&B[bkp][bcq*8]     = make_uint4(w[0], w[1], w[2], w[3]);
        *(uint4*)&B[bkp][bcq*8 + 4] = make_uint4(w[4], w[5], w[6], w[7]);
    };

    float acc[4][4][4];
    #pragma unroll
    for (int mt = 0; mt < 4; mt++)
        #pragma unroll
        for (int nt = 0; nt < 4; nt++)
            #pragma unroll
            for (int q = 0; q < 4; q++) acc[mt][nt][q] = 0.f;

    if (tid < 128) stageB(0, Bs[0]);
    __syncthreads();

    for (int c = 0; c < 16; c++) {
        int cur = c & 1;
        if (c < 15 && tid < 128) stageB(c + 1, Bs[cur ^ 1]);

        #pragma unroll
        for (int s = 0; s < 2; s++) {
            uint32_t b[4][2];
            #pragma unroll
            for (int nt = 0; nt < 4; nt++) {
                int nb = warp_n * 32 + nt * 8 + g;
                int kr = s * 8 + t4;
                b[nt][0] = Bs[cur][kr][nb];    b[nt][1] = Bs[cur][kr+4][nb];
            }
            #pragma unroll
            for (int mt = 0; mt < 4; mt++) {
                int tau = rt * 16 + warp_m * 4 + mt;
                const uint4 v = *(const uint4*)(g_afrag + (((tau*16 + c)*2 + s)*128 + lane*4));
                uint32_t a[4] = {v.x, v.y, v.z, v.w};
                #pragma unroll
                for (int nt = 0; nt < 4; nt++)
                    mma_f16(acc[mt][nt], a, b[nt]);
            }
        }
        __syncthreads();
    }

    // --- epilogue: store S (guard row < 500) ---
    const int row0 = rt * 256;
    #pragma unroll
    for (int mt = 0; mt < 4; mt++) {
        int rowa = row0 + warp_m * 64 + mt * 16 + g;
        int rowb = rowa + 8;
        #pragma unroll
        for (int nt = 0; nt < 4; nt++) {
            int col = warp_n * 32 + nt * 8 + 2 * t4;
            if (rowa < NN)
                *(float2*)(Sg + (long)rowa * HID + col) = make_float2(acc[mt][nt][0], acc[mt][nt][1]);
            if (rowb < NN)
                *(float2*)(Sg + (long)rowb * HID + col) = make_float2(acc[mt][nt][2], acc[mt][nt][3]);
        }
    }

    // --- BN stats: rows >= 500 are exactly zero (zero A rows) ---
    float ls[8], lq[8];
    #pragma unroll
    for (int nt = 0; nt < 4; nt++)
        #pragma unroll
        for (int b = 0; b < 2; b++) {
            float s0 = 0.f, q0 = 0.f;
            #pragma unroll
            for (int mt = 0; mt < 4; mt++) {
                float v0 = acc[mt][nt][b], v1 = acc[mt][nt][b+2];
                s0 += v0 + v1;
                q0 += v0*v0 + v1*v1;
            }
            ls[nt*2+b] = s0;
            lq[nt*2+b] = q0;
        }
    #pragma unroll
    for (int i = 0; i < 8; i++) {
        #pragma unroll
        for (int off = 4; off <= 16; off <<= 1) {
            ls[i] += __shfl_xor_sync(0xFFFFFFFFu, ls[i], off);
            lq[i] += __shfl_xor_sync(0xFFFFFFFFu, lq[i], off);
        }
    }
    if (lane < 4) {
        #pragma unroll
        for (int nt = 0; nt < 4; nt++)
            #pragma unroll
            for (int b = 0; b < 2; b++) {
                ssum[wid][nt*8 + 2*lane + b] = ls[nt*2+b];
                ssq [wid][nt*8 + 2*lane + b] = lq[nt*2+b];
            }
    }
    __syncthreads();
    if (tid < 128) {
        int col = tid & 63;
        int wn = col >> 5, lc = col & 31;
        bool isq = tid >= 64;
        float t = 0.f;
        #pragma unroll
        for (int w = 0; w < 4; w++) {
            int wd = w * 2 + wn;
            t += isq ? ssq[wd][lc] : ssum[wd][lc];
        }
        atomicAdd(isq ? &g_sumsq[col] : &g_sum[col], t);
    }
}

// ---------------- tensor-core GEMM: fp16 2-way split, m16n8k16, fp32 accum ------
// (validated in R10-R13; used for the fused layer GEMMs + final)
template<int K, int C, bool ACCUM, bool FUSE, bool WRITE_H, bool OUT_HALF>
__global__ __launch_bounds__(256) void gemm_tc(
    const float* __restrict__ A, const float* __restrict__ R, float* __restrict__ Hout,
    const float* __restrict__ Bw, const float* __restrict__ bias, void* __restrict__ Cout)
{
    __shared__ uint32_t AsH[128][20], AsL[128][20];
    __shared__ uint32_t BsH[16][72],  BsL[16][72];
    __shared__ float s_scale[HID], s_shift[HID];

    const int tid = threadIdx.x;
    const int wid = tid >> 5;
    const int lane = tid & 31;
    const int g  = lane >> 2;
    const int t4 = lane & 3;
    const int warp_m = wid >> 1;
    const int warp_n = wid & 1;

    const long row0 = (long)blockIdx.x * 128;
    const int col0 = blockIdx.y * 64;

    if (FUSE) {
        if (tid < HID) s_scale[tid] = g_scale[tid];
        else if (tid < 2*HID) s_shift[tid - HID] = g_shift[tid - HID];
        __syncthreads();
    }

    float acc[2][4][4];
    #pragma unroll
    for (int mt = 0; mt < 2; mt++)
        #pragma unroll
        for (int nt = 0; nt < 4; nt++)
            #pragma unroll
            for (int q = 0; q < 4; q++) acc[mt][nt][q] = 0.f;

    for (int k0 = 0; k0 < K; k0 += 32) {
        #pragma unroll
        for (int i = 0; i < 4; i++) {
            int idx = tid + i * 256;
            int r = idx >> 3;
            int q = idx & 7;
            long off = (row0 + r) * K + (k0 + q * 4);
            float4 v = *(const float4*)(A + off);
            if (FUSE) {
                int kc = k0 + q * 4;
                float4 rv = *(const float4*)(R + off);
                v.x = fmaxf(v.x * s_scale[kc+0] + s_shift[kc+0], 0.f) + rv.x;
                v.y = fmaxf(v.y * s_scale[kc+1] + s_shift[kc+1], 0.f) + rv.y;
                v.z = fmaxf(v.z * s_scale[kc+2] + s_shift[kc+2], 0.f) + rv.z;
                v.w = fmaxf(v.w * s_scale[kc+3] + s_shift[kc+3], 0.f) + rv.w;
                if (WRITE_H) *(float4*)(Hout + off) = v;
            }
            uint32_t h01, l01, h23, l23;
            f16_split2(v.x, v.y, h01, l01);
            f16_split2(v.z, v.w, h23, l23);
            *(uint2*)&AsH[r][q*2] = make_uint2(h01, h23);
            *(uint2*)&AsL[r][q*2] = make_uint2(l01, l23);
        }
        {
            int kk = tid >> 4;
            int cq = tid & 15;
            int c = col0 + cq * 4;
            float4 v0 = make_float4(0.f,0.f,0.f,0.f);
            float4 v1 = make_float4(0.f,0.f,0.f,0.f);
            if ((C & 63) == 0 || c < C) {
                v0 = *(const float4*)(Bw + (k0 + 2*kk    ) * C + c);
                v1 = *(const float4*)(Bw + (k0 + 2*kk + 1) * C + c);
            }
            uint32_t h, l;
            f16_split2(v0.x, v1.x, h, l); BsH[kk][cq*4+0] = h; BsL[kk][cq*4+0] = l;
            f16_split2(v0.y, v1.y, h, l); BsH[kk][cq*4+1] = h; BsL[kk][cq*4+1] = l;
            f16_split2(v0.z, v1.z, h, l); BsH[kk][cq*4+2] = h; BsL[kk][cq*4+2] = l;
            f16_split2(v0.w, v1.w, h, l); BsH[kk][cq*4+3] = h; BsL[kk][cq*4+3] = l;
        }
        __syncthreads();

        #pragma unroll
        for (int s = 0; s < 2; s++) {
            uint32_t ah[2][4], al[2][4];
            #pragma unroll
            for (int mt = 0; mt < 2; mt++) {
                int r = warp_m * 32 + mt * 16 + g;
                int kc = s * 8 + t4;
                ah[mt][0] = AsH[r][kc];     al[mt][0] = AsL[r][kc];
                ah[mt][1] = AsH[r+8][kc];   al[mt][1] = AsL[r+8][kc];
                ah[mt][2] = AsH[r][kc+4];   al[mt][2] = AsL[r][kc+4];
                ah[mt][3] = AsH[r+8][kc+4]; al[mt][3] = AsL[r+8][kc+4];
            }
            uint32_t bh[4][2], bl[4][2];
            #pragma unroll
            for (int nt = 0; nt < 4; nt++) {
                int nb = warp_n * 32 + nt * 8 + g;
                int kr = s * 8 + t4;
                bh[nt][0] = BsH[kr][nb];    bl[nt][0] = BsL[kr][nb];
                bh[nt][1] = BsH[kr+4][nb];  bl[nt][1] = BsL[kr+4][nb];
            }
            #pragma unroll
            for (int mt = 0; mt < 2; mt++)
                #pragma unroll
                for (int nt = 0; nt < 4; nt++) {
                    mma_f16(acc[mt][nt], ah[mt], bh[nt]);
                    mma_f16(acc[mt][nt], ah[mt], bl[nt]);
                    mma_f16(acc[mt][nt], al[mt], bh[nt]);
                }
        }
        __syncthreads();
    }

    #pragma unroll
    for (int mt = 0; mt < 2; mt++) {
        long rowa = row0 + warp_m * 32 + mt * 16 + g;
        long rowb = rowa + 8;
        #pragma unroll
        for (int nt = 0; nt < 4; nt++) {
            int col = col0 + warp_n * 32 + nt * 8 + 2 * t4;
            if ((C & 63) == 0 || col < C) {
                float bx = bias[col];
                float by = bias[col + 1];
                float2 v0 = make_float2(acc[mt][nt][0] + bx, acc[mt][nt][1] + by);
                float2 v1 = make_float2(acc[mt][nt][2] + bx, acc[mt][nt][3] + by);
                if (OUT_HALF) {
                    __half2* o = (__half2*)Cout;
                    o[(rowa * C + col) >> 1] = __floats2half2_rn(v0.x, v0.y);
                    o[(rowb * C + col) >> 1] = __floats2half2_rn(v1.x, v1.y);
                } else {
                    float* d0 = (float*)Cout + rowa * C + col;
                    float* d1 = (float*)Cout + rowb * C + col;
                    if (ACCUM) {
                        float2 o0 = *(const float2*)d0;
                        float2 o1 = *(const float2*)d1;
                        v0.x += o0.x; v0.y += o0.y;
                        v1.x += o1.x; v1.y += o1.y;
                    }
                    *(float2*)d0 = v0;
                    *(float2*)d1 = v1;
                }
            }
        }
    }
}

// ---------------- fused input GEMM (x read ONCE): t0, r0, AND out=x@w_fr+b_fr ----
#define IN3_SMEM_WORDS (2 * 128 * 52)
#define IN3_SMEM_BYTES (IN3_SMEM_WORDS * 4)

__global__ __launch_bounds__(256) void gemm_in3(
    const float* __restrict__ A,
    const float* __restrict__ w_g0, const float* __restrict__ b_g0, __half2* __restrict__ T,
    const float* __restrict__ w_r0, const float* __restrict__ b_r0, float* __restrict__ Rr,
    const float* __restrict__ w_fr, const float* __restrict__ b_fr, float* __restrict__ Out)
{
    extern __shared__ uint32_t dsm[];
    uint32_t (*AsH)[52] = (uint32_t(*)[52])(dsm);
    uint32_t (*AsL)[52] = (uint32_t(*)[52])(dsm + 128*52);
    __shared__ uint32_t BsH[16][72], BsL[16][72];

    const int tid = threadIdx.x;
    const int wid = tid >> 5;
    const int lane = tid & 31;
    const int g  = lane >> 2;
    const int t4 = lane & 3;
    const int warp_m = wid >> 1;
    const int warp_n = wid & 1;
    const long row0 = (long)blockIdx.x * 128;

    #pragma unroll
    for (int i = 0; i < 12; i++) {
        int idx = tid + i * 256;
        int r = idx / 24;
        int q = idx % 24;
        float4 v = *(const float4*)(A + (row0 + r) * FIN + q * 4);
        uint32_t h01, l01, h23, l23;
        f16_split2(v.x, v.y, h01, l01);
        f16_split2(v.z, v.w, h23, l23);
        *(uint2*)&AsH[r][q*2] = make_uint2(h01, h23);
        *(uint2*)&AsL[r][q*2] = make_uint2(l01, l23);
    }

    const float* Bws[4]   = {w_g0, w_r0, w_fr, w_fr};
    const float* biass[4] = {b_g0, b_r0, b_fr, b_fr};

    #pragma unroll 1
    for (int phase = 0; phase < 4; phase++) {
        const float* Bw  = Bws[phase];
        const float* bia = biass[phase];
        const int col0 = (phase == 3) ? 64 : 0;
        const int C = (phase >= 2) ? OUTF : HID;

        float acc[2][4][4];
        #pragma unroll
        for (int mt = 0; mt < 2; mt++)
            #pragma unroll
            for (int nt = 0; nt < 4; nt++)
                #pragma unroll
                for (int q = 0; q < 4; q++) acc[mt][nt][q] = 0.f;

        for (int chunk = 0; chunk < 3; chunk++) {
            int k0 = chunk * 32;
            __syncthreads();
            {
                int kk = tid >> 4;
                int cq = tid & 15;
                int c = col0 + cq * 4;
                float4 v0 = make_float4(0.f,0.f,0.f,0.f);
                float4 v1 = make_float4(0.f,0.f,0.f,0.f);
                if (c < C) {
                    v0 = *(const float4*)(Bw + (k0 + 2*kk    ) * C + c);
                    v1 = *(const float4*)(Bw + (k0 + 2*kk + 1) * C + c);
                }
                uint32_t h, l;
                f16_split2(v0.x, v1.x, h, l); BsH[kk][cq*4+0] = h; BsL[kk][cq*4+0] = l;
                f16_split2(v0.y, v1.y, h, l); BsH[kk][cq*4+1] = h; BsL[kk][cq*4+1] = l;
                f16_split2(v0.z, v1.z, h, l); BsH[kk][cq*4+2] = h; BsL[kk][cq*4+2] = l;
                f16_split2(v0.w, v1.w, h, l); BsH[kk][cq*4+3] = h; BsL[kk][cq*4+3] = l;
            }
            __syncthreads();

            #pragma unroll
            for (int s = 0; s < 2; s++) {
                uint32_t ah[2][4], al[2][4];
                #pragma unroll
                for (int mt = 0; mt < 2; mt++) {
                    int r = warp_m * 32 + mt * 16 + g;
                    int kc = chunk * 16 + s * 8 + t4;
                    ah[mt][0] = AsH[r][kc];     al[mt][0] = AsL[r][kc];
                    ah[mt][1] = AsH[r+8][kc];   al[mt][1] = AsL[r+8][kc];
                    ah[mt][2] = AsH[r][kc+4];   al[mt][2] = AsL[r][kc+4];
                    ah[mt][3] = AsH[r+8][kc+4]; al[mt][3] = AsL[r+8][kc+4];
                }
                uint32_t bh[4][2], bl[4][2];
                #pragma unroll
                for (int nt = 0; nt < 4; nt++) {
                    int nb = warp_n * 32 + nt * 8 + g;
                    int kr = s * 8 + t4;
                    bh[nt][0] = BsH[kr][nb];    bl[nt][0] = BsL[kr][nb];
                    bh[nt][1] = BsH[kr+4][nb];  bl[nt][1] = BsL[kr+4][nb];
                }
                #pragma unroll
                for (int mt = 0; mt < 2; mt++)
                    #pragma unroll
                    for (int nt = 0; nt < 4; nt++) {
                        mma_f16(acc[mt][nt], ah[mt], bh[nt]);
                        mma_f16(acc[mt][nt], ah[mt], bl[nt]);
                        mma_f16(acc[mt][nt], al[mt], bh[nt]);
                    }
            }
        }

        #pragma unroll
        for (int mt = 0; mt < 2; mt++) {
            long rowa = row0 + warp_m * 32 + mt * 16 + g;
            long rowb = rowa + 8;
            #pragma unroll
            for (int nt = 0; nt < 4; nt++) {
                int col = col0 + warp_n * 32 + nt * 8 + 2 * t4;
                if (col < C) {
                    float bx = bia[col];
                    float by = bia[col + 1];
                    float2 v0 = make_float2(acc[mt][nt][0] + bx, acc[mt][nt][1] + by);
                    float2 v1 = make_float2(acc[mt][nt][2] + bx, acc[mt][nt][3] + by);
                    if (phase == 0) {
                        T[(rowa * HID + col) >> 1] = __floats2half2_rn(v0.x, v0.y);
                        T[(rowb * HID + col) >> 1] = __floats2half2_rn(v1.x, v1.y);
                    } else if (phase == 1) {
                        *(float2*)(Rr + rowa * HID + col) = v0;
                        *(float2*)(Rr + rowb * HID + col) = v1;
                    } else {
                        *(float2*)(Out + rowa * OUTF + col) = v0;
                        *(float2*)(Out + rowb * OUTF + col) = v1;
                    }
                }
            }
        }
    }
}

// ---------------- BN finalize ----------------
__global__ void bn_finalize(const float* __restrict__ gamma, const float* __restrict__ beta) {
    int c = threadIdx.x;
    float s = g_sum[c], q = g_sumsq[c];
    const float inv = 1.f / (float)ROWS;
    float mean = s * inv;
    float var = q * inv - mean * mean;
    float rstd = rsqrtf(var + BN_EPS);
    float a = rstd * gamma[c];
    g_scale[c] = a;
    g_shift[c] = beta[c] - mean * a;
    g_sum[c] = 0.f; g_sumsq[c] = 0.f;
}

// ---------------- launch ----------------
extern "C" void kernel_launch(void* const* d_in, const int* in_sizes, int n_in,
                              void* d_out, int out_size)
{
    const float* x     = (const float*)d_in[0];
    const float* adj   = (const float*)d_in[1];
    const float* w_g0  = (const float*)d_in[2];
    const float* b_g0  = (const float*)d_in[3];
    const float* w_g1  = (const float*)d_in[4];
    const float* b_g1  = (const float*)d_in[5];
    const float* w_g2  = (const float*)d_in[6];
    const float* b_g2  = (const float*)d_in[7];
    const float* gamma = (const float*)d_in[8];
    const float* beta  = (const float*)d_in[9];
    const float* w_r0  = (const float*)d_in[10];
    const float* b_r0  = (const float*)d_in[11];
    const float* w_fc  = (const float*)d_in[12];
    const float* b_fc  = (const float*)d_in[13];
    const float* w_fr  = (const float*)d_in[14];
    const float* b_fr  = (const float*)d_in[15];
    float* out = (float*)d_out;

    __half2 *pt16;
    float *ps, *ph, *pr;
    cudaGetSymbolAddress((void**)&pt16, g_t16);
    cudaGetSymbolAddress((void**)&ps, g_s);
    cudaGetSymbolAddress((void**)&ph, g_h);
    cudaGetSymbolAddress((void**)&pr, g_r);

    const int ROWB = ROWS / 128;               // 2000

    cudaFuncSetAttribute(gemm_in3,
                         cudaFuncAttributeMaxDynamicSharedMemorySize, IN3_SMEM_BYTES);

    // #0: t0 = fp16(x@w_g0+b0), r0 = x@w_r0+b_r0, out = x@w_fr+b_fr (x read once)
    gemm_in3<<<ROWB, 256, IN3_SMEM_BYTES>>>(x, w_g0, b_g0, pt16,
                                            w_r0, b_r0, pr,
                                            w_fr, b_fr, out);

    // #1,#2: fragment-major fp16 a_hat (deterministic)
    prep_deg<<<NN, 128>>>(adj);
    prep_fill_frag<<<512, 256>>>(adj);

    // #3: layer-0 SpMM-as-MMA (M=256/block)  ← ncu capture slot
    spmm_mma<<<dim3(2, GG), 256>>>(pt16, ps);
    bn_finalize<<<1, HID>>>(gamma + 0 * HID, beta + 0 * HID);

    // layer 0 fused: h0 = relu(bn(s)) + r0; t1 = fp16(h0 @ w_g1 + b)
    gemm_tc<HID, HID, false, true, true, true><<<dim3(ROWB, 1), 256>>>(ps, pr, ph, w_g1, b_g1, pt16);

    // layer 1
    spmm_mma<<<dim3(2, GG), 256>>>(pt16, ps);
    bn_finalize<<<1, HID>>>(gamma + 1 * HID, beta + 1 * HID);
    gemm_tc<HID, HID, false, true, true, true><<<dim3(ROWB, 1), 256>>>(ps, ph, ph, w_g2, b_g2, pt16);

    // layer 2: h2 never materialized; out += h2 @ w_fc + b_fc
    spmm_mma<<<dim3(2, GG), 256>>>(pt16, ps);
    bn_finalize<<<1, HID>>>(gamma + 2 * HID, beta + 2 * HID);
    gemm_tc<HID, OUTF, true, true, false, false><<<dim3(ROWB, 2), 256>>>(ps, ph, nullptr, w_fc, b_fc, out);
}

// round 15
// speedup vs baseline: 1.0460x; 1.0460x over previous
#include <cuda_runtime.h>
#include <cuda_fp16.h>
#include <cstdint>

#define GG 512            // B*T graphs
#define NN 500            // nodes
#define NP 512            // padded node count (MMA K/M)
#define FIN 96
#define HID 64
#define OUTF 96
#define ROWS (GG*NN)      // 256000
#define BN_EPS 1e-5f

// weight-fragment table offsets (uint32 words); layout per matrix block:
//   (((colblk*chunks + chunk)*2 + s)*2 + warp_n)*32*16 + lane*16 + j
//   j: 0..7 = hi words (nt*2+reg), 8..15 = lo words
#define WOFF_G0 0          // K=96, C=64, chunks=3, nblk=1 -> 6144
#define WOFF_R0 6144
#define WOFF_FR 12288      // K=96, C=96, chunks=3, nblk=2 -> 12288
#define WOFF_G1 24576      // K=64, C=64, chunks=2 -> 4096
#define WOFF_G2 28672
#define WOFF_FC 32768      // K=64, C=96, chunks=2, nblk=2 -> 8192
#define WFRAG_WORDS 40960

// ---------------- scratch (device globals; no allocation allowed) ----------------
__device__ __half2 g_t16[((long)ROWS + 16)*HID/2]; // GEMM output / SpMM input (fp16)
__device__ uint32_t g_afrag[32*16*2*128];          // a_hat fragments, 512KB
__device__ uint32_t g_wfrag[WFRAG_WORDS];          // weight fragments, 160KB
__device__ float g_s[(long)ROWS*HID];    // SpMM output
__device__ float g_h[(long)ROWS*HID];    // layer activations (residual chain)
__device__ float g_r[(long)ROWS*HID];    // layer-0 residual
__device__ float g_dinv[NN];
__device__ float g_sum[HID];
__device__ float g_sumsq[HID];
__device__ float g_scale[HID];
__device__ float g_shift[HID];

// ---------------- fp16 helpers ----------------
__device__ __forceinline__ uint32_t h2u(__half2 h) { return *(uint32_t*)&h; }

__device__ __forceinline__ void f16_split2(float a, float b, uint32_t& hi, uint32_t& lo) {
    __half2 h = __floats2half2_rn(a, b);
    float2 back = __half22float2(h);
    __half2 l = __floats2half2_rn(a - back.x, b - back.y);
    hi = h2u(h); lo = h2u(l);
}

__device__ __forceinline__ void mma_f16(float* c, const uint32_t* a, const uint32_t* b) {
    asm volatile(
        "mma.sync.aligned.m16n8k16.row.col.f32.f16.f16.f32 "
        "{%0,%1,%2,%3}, {%4,%5,%6,%7}, {%8,%9}, {%0,%1,%2,%3};\n"
        : "+f"(c[0]), "+f"(c[1]), "+f"(c[2]), "+f"(c[3])
        : "r"(a[0]), "r"(a[1]), "r"(a[2]), "r"(a[3]), "r"(b[0]), "r"(b[1]));
}

// ---------------- prep 1: degrees (blocks 0..499) + weight fragments (500+) ----
__device__ __forceinline__ void fill_wfrag_word(
    int m, const float* __restrict__ W, int K, int C, int chunks)
{
    int rem  = m & 2047;
    int cbch = m >> 11;                 // colblk*chunks + chunk
    int chunk = cbch % chunks;
    int colblk = cbch / chunks;
    int s    = (rem >> 10) & 1;
    int wn   = (rem >> 9) & 1;
    int lane = (rem >> 4) & 31;
    int j    = rem & 15;
    int reg  = j & 1;
    int nt   = (j >> 1) & 3;
    bool islo = j >= 8;
    int col = colblk * 64 + wn * 32 + nt * 8 + (lane >> 2);
    int kpl = s * 8 + (lane & 3) + reg * 4;
    int k0  = chunk * 32 + 2 * kpl;
    float v0 = 0.f, v1 = 0.f;
    if (col < C) {
        v0 = W[(long)k0 * C + col];
        v1 = W[(long)(k0 + 1) * C + col];
    }
    uint32_t hi, lo;
    f16_split2(v0, v1, hi, lo);
    return (void)(g_wfrag[0]), (void)0;  // placeholder (never reached; see caller)
}

__global__ void prep_deg_w(const float* __restrict__ adj,
    const float* __restrict__ w_g0, const float* __restrict__ w_r0,
    const float* __restrict__ w_fr, const float* __restrict__ w_g1,
    const float* __restrict__ w_g2, const float* __restrict__ w_fc)
{
    int tid = threadIdx.x;
    if (blockIdx.x < NN) {
        int m = blockIdx.x;
        float sum = 0.f;
        for (int n = tid; n < NN; n += blockDim.x) sum += adj[m*NN + n];
        __shared__ float ssum[4];
        #pragma unroll
        for (int o = 16; o; o >>= 1) sum += __shfl_down_sync(0xFFFFFFFFu, sum, o);
        int w = tid >> 5;
        if ((tid & 31) == 0) ssum[w] = sum;
        __syncthreads();
        if (tid == 0)
            g_dinv[m] = rsqrtf(1.f + ssum[0] + ssum[1] + ssum[2] + ssum[3]);
        if (blockIdx.x == 0 && tid < HID) { g_sum[tid] = 0.f; g_sumsq[tid] = 0.f; }
        return;
    }
    int idx = (blockIdx.x - NN) * 128 + tid;     // 0..40959
    const float* W; int K, C, chunks, m;
    if (idx < WOFF_R0)      { W = w_g0; K=96; C=64; chunks=3; m = idx; }
    else if (idx < WOFF_FR) { W = w_r0; K=96; C=64; chunks=3; m = idx - WOFF_R0; }
    else if (idx < WOFF_G1) { W = w_fr; K=96; C=96; chunks=3; m = idx - WOFF_FR; }
    else if (idx < WOFF_G2) { W = w_g1; K=64; C=64; chunks=2; m = idx - WOFF_G1; }
    else if (idx < WOFF_FC) { W = w_g2; K=64; C=64; chunks=2; m = idx - WOFF_G2; }
    else                    { W = w_fc; K=64; C=96; chunks=2; m = idx - WOFF_FC; }
    int rem  = m & 2047;
    int cbch = m >> 11;
    int chunk = cbch % chunks;
    int colblk = cbch / chunks;
    int s    = (rem >> 10) & 1;
    int wn   = (rem >> 9) & 1;
    int lane = (rem >> 4) & 31;
    int j    = rem & 15;
    int reg  = j & 1;
    int nt   = (j >> 1) & 3;
    int col = colblk * 64 + wn * 32 + nt * 8 + (lane >> 2);
    int kpl = s * 8 + (lane & 3) + reg * 4;
    int k0  = chunk * 32 + 2 * kpl;
    float v0 = 0.f, v1 = 0.f;
    if (col < C) {
        v0 = W[(long)k0 * C + col];
        v1 = W[(long)(k0 + 1) * C + col];
    }
    uint32_t hi, lo;
    f16_split2(v0, v1, hi, lo);
    g_wfrag[idx] = (j >= 8) ? lo : hi;
}

// ---------------- prep 2: fragment-major fp16 a_hat ----------------
__device__ __forceinline__ float ahat_val(const float* adj, const float* dinv, int m, int n) {
    if (m >= NN || n >= NN) return 0.f;
    float dm = dinv[m];
    return (n == m) ? dm * dm : adj[m*NN + n] * dm * dinv[n];
}

__global__ __launch_bounds__(256) void prep_fill_frag(const float* __restrict__ adj) {
    __shared__ float sdinv[NN];
    int tid = threadIdx.x;
    for (int i = tid; i < NN; i += 256) sdinv[i] = g_dinv[i];
    __syncthreads();
    int idx = blockIdx.x * 256 + tid;           // 0 .. 131071
    int reg = idx & 3;
    int l   = (idx >> 2) & 31;
    int s   = (idx >> 7) & 1;
    int c   = (idx >> 8) & 15;
    int tau = idx >> 12;
    int g = l >> 2, t4 = l & 3;
    int row = tau * 16 + g + (reg & 1) * 8;
    int kp  = c * 16 + s * 8 + t4 + (reg >> 1) * 4;
    __half2 v = __floats2half2_rn(ahat_val(adj, sdinv, row, 2*kp),
                                  ahat_val(adj, sdinv, row, 2*kp + 1));
    g_afrag[idx] = *(uint32_t*)&v;
}

// ---------------- SpMM as batched dense MMA + fused BN stats (R13 config) --------
__global__ __launch_bounds__(256) void spmm_mma(
    const __half2* __restrict__ T2, float* __restrict__ S)
{
    __shared__ uint32_t Bs[2][16][72];
    __shared__ float ssum[8][32], ssq[8][32];

    const int tid = threadIdx.x;
    const int wid = tid >> 5;
    const int lane = tid & 31;
    const int g  = lane >> 2;
    const int t4 = lane & 3;
    const int warp_m = wid >> 1;
    const int warp_n = wid & 1;

    const int gph = blockIdx.y;
    const int rt = blockIdx.x;
    const __half* Tg = (const __half*)T2 + (long)gph * NN * HID;
    float* Sg = S + (long)gph * NN * HID;

    const int bkp = tid >> 3;
    const int bcq = tid & 7;

    auto stageB = [&](int c, uint32_t (*B)[72]) {
        long k = c * 32 + 2 * bkp;
        uint4 lo = *(const uint4*)(Tg + k * HID + bcq * 8);
        uint4 hi = *(const uint4*)(Tg + (k + 1) * HID + bcq * 8);
        const __half2* l2 = (const __half2*)&lo;
        const __half2* h2 = (const __half2*)&hi;
        uint32_t w[8];
        #pragma unroll
        for (int j = 0; j < 4; j++) {
            w[2*j]   = h2u(__lows2half2(l2[j], h2[j]));
            w[2*j+1] = h2u(__highs2half2(l2[j], h2[j]));
        }
        *(uint4*)&B[bkp][bcq*8]     = make_uint4(w[0], w[1], w[2], w[3]);
        *(uint4*)&B[bkp][bcq*8 + 4] = make_uint4(w[4], w[5], w[6], w[7]);
    };

    float acc[2][4][4];
    #pragma unroll
    for (int mt = 0; mt < 2; mt++)
        #pragma unroll
        for (int nt = 0; nt < 4; nt++)
            #pragma unroll
            for (int q = 0; q < 4; q++) acc[mt][nt][q] = 0.f;

    if (tid < 128) stageB(0, Bs[0]);
    __syncthreads();

    for (int c = 0; c < 16; c++) {
        int cur = c & 1;
        if (c < 15 && tid < 128) stageB(c + 1, Bs[cur ^ 1]);

        #pragma unroll
        for (int s = 0; s < 2; s++) {
            uint32_t a[2][4], b[4][2];
            #pragma unroll
            for (int mt = 0; mt < 2; mt++) {
                int tau = rt * 8 + warp_m * 2 + mt;
                const uint4 v = *(const uint4*)(g_afrag + (((tau*16 + c)*2 + s)*128 + lane*4));
                a[mt][0] = v.x; a[mt][1] = v.y; a[mt][2] = v.z; a[mt][3] = v.w;
            }
            #pragma unroll
            for (int nt = 0; nt < 4; nt++) {
                int nb = warp_n * 32 + nt * 8 + g;
                int kr = s * 8 + t4;
                b[nt][0] = Bs[cur][kr][nb];    b[nt][1] = Bs[cur][kr+4][nb];
            }
            #pragma unroll
            for (int mt = 0; mt < 2; mt++)
                #pragma unroll
                for (int nt = 0; nt < 4; nt++)
                    mma_f16(acc[mt][nt], a[mt], b[nt]);
        }
        __syncthreads();
    }

    const int row0 = rt * 128;
    #pragma unroll
    for (int mt = 0; mt < 2; mt++) {
        int rowa = row0 + warp_m * 32 + mt * 16 + g;
        int rowb = rowa + 8;
        #pragma unroll
        for (int nt = 0; nt < 4; nt++) {
            int col = warp_n * 32 + nt * 8 + 2 * t4;
            if (rowa < NN)
                *(float2*)(Sg + (long)rowa * HID + col) = make_float2(acc[mt][nt][0], acc[mt][nt][1]);
            if (rowb < NN)
                *(float2*)(Sg + (long)rowb * HID + col) = make_float2(acc[mt][nt][2], acc[mt][nt][3]);
        }
    }

    float ls[8], lq[8];
    #pragma unroll
    for (int nt = 0; nt < 4; nt++)
        #pragma unroll
        for (int b = 0; b < 2; b++) {
            float v0 = acc[0][nt][b], v1 = acc[0][nt][b+2];
            float v2 = acc[1][nt][b], v3 = acc[1][nt][b+2];
            ls[nt*2+b] = v0 + v1 + v2 + v3;
            lq[nt*2+b] = v0*v0 + v1*v1 + v2*v2 + v3*v3;
        }
    #pragma unroll
    for (int i = 0; i < 8; i++) {
        #pragma unroll
        for (int off = 4; off <= 16; off <<= 1) {
            ls[i] += __shfl_xor_sync(0xFFFFFFFFu, ls[i], off);
            lq[i] += __shfl_xor_sync(0xFFFFFFFFu, lq[i], off);
        }
    }
    if (lane < 4) {
        #pragma unroll
        for (int nt = 0; nt < 4; nt++)
            #pragma unroll
            for (int b = 0; b < 2; b++) {
                ssum[wid][nt*8 + 2*lane + b] = ls[nt*2+b];
                ssq [wid][nt*8 + 2*lane + b] = lq[nt*2+b];
            }
    }
    __syncthreads();
    if (tid < 128) {
        int col = tid & 63;
        int wn = col >> 5, lc = col & 31;
        bool isq = tid >= 64;
        float t = 0.f;
        #pragma unroll
        for (int w = 0; w < 4; w++) {
            int wd = w * 2 + wn;
            t += isq ? ssq[wd][lc] : ssum[wd][lc];
        }
        atomicAdd(isq ? &g_sumsq[col] : &g_sum[col], t);
    }
}

// ---------------- tensor-core GEMM v2: B from fragment-major global ------------
// A staged+split ONCE for full K (K<=64 here); 1 sync; k-loop is LDS-A + LDG-B + MMA.
template<int K, int C, bool ACCUM, bool FUSE, bool WRITE_H, bool OUT_HALF>
__global__ __launch_bounds__(256) void gemm_tc(
    const float* __restrict__ A, const float* __restrict__ R, float* __restrict__ Hout,
    const float* __restrict__ bias, void* __restrict__ Cout,
    const uint32_t* __restrict__ wf)
{
    constexpr int KP = K / 2;
    constexpr int ST = KP + 4;
    constexpr int CHUNKS = K / 32;
    __shared__ uint32_t AsH[128][ST], AsL[128][ST];
    __shared__ float s_scale[HID], s_shift[HID];

    const int tid = threadIdx.x;
    const int wid = tid >> 5;
    const int lane = tid & 31;
    const int g  = lane >> 2;
    const int t4 = lane & 3;
    const int warp_m = wid >> 1;
    const int warp_n = wid & 1;

    const long row0 = (long)blockIdx.x * 128;
    const int colblk = blockIdx.y;
    const int col0 = colblk * 64;

    if (FUSE) {
        if (tid < HID) s_scale[tid] = g_scale[tid];
        else if (tid < 2*HID) s_shift[tid - HID] = g_shift[tid - HID];
        __syncthreads();
    }

    // stage + split FULL A tile: 128 rows x K
    #pragma unroll
    for (int i = 0; i < K / 8; i++) {
        int idx = tid + i * 256;
        int r = idx / (K / 4);
        int q = idx % (K / 4);
        long off = (row0 + r) * K + q * 4;
        float4 v = *(const float4*)(A + off);
        if (FUSE) {
            int kc = q * 4;
            float4 rv = *(const float4*)(R + off);
            v.x = fmaxf(v.x * s_scale[kc+0] + s_shift[kc+0], 0.f) + rv.x;
            v.y = fmaxf(v.y * s_scale[kc+1] + s_shift[kc+1], 0.f) + rv.y;
            v.z = fmaxf(v.z * s_scale[kc+2] + s_shift[kc+2], 0.f) + rv.z;
            v.w = fmaxf(v.w * s_scale[kc+3] + s_shift[kc+3], 0.f) + rv.w;
            if (WRITE_H) *(float4*)(Hout + off) = v;
        }
        uint32_t h01, l01, h23, l23;
        f16_split2(v.x, v.y, h01, l01);
        f16_split2(v.z, v.w, h23, l23);
        *(uint2*)&AsH[r][q*2] = make_uint2(h01, h23);
        *(uint2*)&AsL[r][q*2] = make_uint2(l01, l23);
    }
    __syncthreads();

    float acc[2][4][4];
    #pragma unroll
    for (int mt = 0; mt < 2; mt++)
        #pragma unroll
        for (int nt = 0; nt < 4; nt++)
            #pragma unroll
            for (int q = 0; q < 4; q++) acc[mt][nt][q] = 0.f;

    #pragma unroll
    for (int chunk = 0; chunk < CHUNKS; chunk++) {
        #pragma unroll
        for (int s = 0; s < 2; s++) {
            const uint32_t* bp = wf +
                ((((colblk * CHUNKS + chunk) * 2 + s) * 2 + warp_n) * 32 + lane) * 16;
            uint4 bh0 = *(const uint4*)(bp);
            uint4 bh1 = *(const uint4*)(bp + 4);
            uint4 bl0 = *(const uint4*)(bp + 8);
            uint4 bl1 = *(const uint4*)(bp + 12);
            uint32_t bh[4][2] = {{bh0.x,bh0.y},{bh0.z,bh0.w},{bh1.x,bh1.y},{bh1.z,bh1.w}};
            uint32_t bl[4][2] = {{bl0.x,bl0.y},{bl0.z,bl0.w},{bl1.x,bl1.y},{bl1.z,bl1.w}};

            uint32_t ah[2][4], al[2][4];
            #pragma unroll
            for (int mt = 0; mt < 2; mt++) {
                int r = warp_m * 32 + mt * 16 + g;
                int kc = chunk * 16 + s * 8 + t4;
                ah[mt][0] = AsH[r][kc];     al[mt][0] = AsL[r][kc];
                ah[mt][1] = AsH[r+8][kc];   al[mt][1] = AsL[r+8][kc];
                ah[mt][2] = AsH[r][kc+4];   al[mt][2] = AsL[r][kc+4];
                ah[mt][3] = AsH[r+8][kc+4]; al[mt][3] = AsL[r+8][kc+4];
            }
            #pragma unroll
            for (int mt = 0; mt < 2; mt++)
                #pragma unroll
                for (int nt = 0; nt < 4; nt++) {
                    mma_f16(acc[mt][nt], ah[mt], bh[nt]);
                    mma_f16(acc[mt][nt], ah[mt], bl[nt]);
                    mma_f16(acc[mt][nt], al[mt], bh[nt]);
                }
        }
    }

    #pragma unroll
    for (int mt = 0; mt < 2; mt++) {
        long rowa = row0 + warp_m * 32 + mt * 16 + g;
        long rowb = rowa + 8;
        #pragma unroll
        for (int nt = 0; nt < 4; nt++) {
            int col = col0 + warp_n * 32 + nt * 8 + 2 * t4;
            if ((C & 63) == 0 || col < C) {
                float bx = bias[col];
                float by = bias[col + 1];
                float2 v0 = make_float2(acc[mt][nt][0] + bx, acc[mt][nt][1] + by);
                float2 v1 = make_float2(acc[mt][nt][2] + bx, acc[mt][nt][3] + by);
                if (OUT_HALF) {
                    __half2* o = (__half2*)Cout;
                    o[(rowa * C + col) >> 1] = __floats2half2_rn(v0.x, v0.y);
                    o[(rowb * C + col) >> 1] = __floats2half2_rn(v1.x, v1.y);
                } else {
                    float* d0 = (float*)Cout + rowa * C + col;
                    float* d1 = (float*)Cout + rowb * C + col;
                    if (ACCUM) {
                        float2 o0 = *(const float2*)d0;
                        float2 o1 = *(const float2*)d1;
                        v0.x += o0.x; v0.y += o0.y;
                        v1.x += o1.x; v1.y += o1.y;
                    }
                    *(float2*)d0 = v0;
                    *(float2*)d1 = v1;
                }
            }
        }
    }
}

// ---------------- fused input GEMM v2 (x read ONCE; B from wfrag; 1 sync) -------
#define IN3_SMEM_WORDS (2 * 128 * 52)
#define IN3_SMEM_BYTES (IN3_SMEM_WORDS * 4)

__global__ __launch_bounds__(256) void gemm_in3(
    const float* __restrict__ A,
    const float* __restrict__ b_g0, __half2* __restrict__ T,
    const float* __restrict__ b_r0, float* __restrict__ Rr,
    const float* __restrict__ b_fr, float* __restrict__ Out)
{
    extern __shared__ uint32_t dsm[];
    uint32_t (*AsH)[52] = (uint32_t(*)[52])(dsm);
    uint32_t (*AsL)[52] = (uint32_t(*)[52])(dsm + 128*52);

    const int tid = threadIdx.x;
    const int wid = tid >> 5;
    const int lane = tid & 31;
    const int g  = lane >> 2;
    const int t4 = lane & 3;
    const int warp_m = wid >> 1;
    const int warp_n = wid & 1;
    const long row0 = (long)blockIdx.x * 128;

    #pragma unroll
    for (int i = 0; i < 12; i++) {
        int idx = tid + i * 256;
        int r = idx / 24;
        int q = idx % 24;
        float4 v = *(const float4*)(A + (row0 + r) * FIN + q * 4);
        uint32_t h01, l01, h23, l23;
        f16_split2(v.x, v.y, h01, l01);
        f16_split2(v.z, v.w, h23, l23);
        *(uint2*)&AsH[r][q*2] = make_uint2(h01, h23);
        *(uint2*)&AsL[r][q*2] = make_uint2(l01, l23);
    }
    __syncthreads();

    const int woffs[4]  = {WOFF_G0, WOFF_R0, WOFF_FR, WOFF_FR};
    const int cblks[4]  = {0, 0, 0, 1};
    const float* biass[4] = {b_g0, b_r0, b_fr, b_fr};

    #pragma unroll 1
    for (int phase = 0; phase < 4; phase++) {
        const float* bia = biass[phase];
        const int col0 = (phase == 3) ? 64 : 0;
        const int C = (phase >= 2) ? OUTF : HID;
        const uint32_t* wf = g_wfrag + woffs[phase];
        const int cb = cblks[phase];

        float acc[2][4][4];
        #pragma unroll
        for (int mt = 0; mt < 2; mt++)
            #pragma unroll
            for (int nt = 0; nt < 4; nt++)
                #pragma unroll
                for (int q = 0; q < 4; q++) acc[mt][nt][q] = 0.f;

        #pragma unroll
        for (int chunk = 0; chunk < 3; chunk++) {
            #pragma unroll
            for (int s = 0; s < 2; s++) {
                const uint32_t* bp = wf +
                    ((((cb * 3 + chunk) * 2 + s) * 2 + warp_n) * 32 + lane) * 16;
                uint4 bh0 = *(const uint4*)(bp);
                uint4 bh1 = *(const uint4*)(bp + 4);
                uint4 bl0 = *(const uint4*)(bp + 8);
                uint4 bl1 = *(const uint4*)(bp + 12);
                uint32_t bh[4][2] = {{bh0.x,bh0.y},{bh0.z,bh0.w},{bh1.x,bh1.y},{bh1.z,bh1.w}};
                uint32_t bl[4][2] = {{bl0.x,bl0.y},{bl0.z,bl0.w},{bl1.x,bl1.y},{bl1.z,bl1.w}};

                uint32_t ah[2][4], al[2][4];
                #pragma unroll
                for (int mt = 0; mt < 2; mt++) {
                    int r = warp_m * 32 + mt * 16 + g;
                    int kc = chunk * 16 + s * 8 + t4;
                    ah[mt][0] = AsH[r][kc];     al[mt][0] = AsL[r][kc];
                    ah[mt][1] = AsH[r+8][kc];   al[mt][1] = AsL[r+8][kc];
                    ah[mt][2] = AsH[r][kc+4];   al[mt][2] = AsL[r][kc+4];
                    ah[mt][3] = AsH[r+8][kc+4]; al[mt][3] = AsL[r+8][kc+4];
                }
                #pragma unroll
                for (int mt = 0; mt < 2; mt++)
                    #pragma unroll
                    for (int nt = 0; nt < 4; nt++) {
                        mma_f16(acc[mt][nt], ah[mt], bh[nt]);
                        mma_f16(acc[mt][nt], ah[mt], bl[nt]);
                        mma_f16(acc[mt][nt], al[mt], bh[nt]);
                    }
            }
        }

        #pragma unroll
        for (int mt = 0; mt < 2; mt++) {
            long rowa = row0 + warp_m * 32 + mt * 16 + g;
            long rowb = rowa + 8;
            #pragma unroll
            for (int nt = 0; nt < 4; nt++) {
                int col = col0 + warp_n * 32 + nt * 8 + 2 * t4;
                if (col < C) {
                    float bx = bia[col];
                    float by = bia[col + 1];
                    float2 v0 = make_float2(acc[mt][nt][0] + bx, acc[mt][nt][1] + by);
                    float2 v1 = make_float2(acc[mt][nt][2] + bx, acc[mt][nt][3] + by);
                    if (phase == 0) {
                        T[(rowa * HID + col) >> 1] = __floats2half2_rn(v0.x, v0.y);
                        T[(rowb * HID + col) >> 1] = __floats2half2_rn(v1.x, v1.y);
                    } else if (phase == 1) {
                        *(float2*)(Rr + rowa * HID + col) = v0;
                        *(float2*)(Rr + rowb * HID + col) = v1;
                    } else {
                        *(float2*)(Out + rowa * OUTF + col) = v0;
                        *(float2*)(Out + rowb * OUTF + col) = v1;
                    }
                }
            }
        }
    }
}

// ---------------- BN finalize ----------------
__global__ void bn_finalize(const float* __restrict__ gamma, const float* __restrict__ beta) {
    int c = threadIdx.x;
    float s = g_sum[c], q = g_sumsq[c];
    const float inv = 1.f / (float)ROWS;
    float mean = s * inv;
    float var = q * inv - mean * mean;
    float rstd = rsqrtf(var + BN_EPS);
    float a = rstd * gamma[c];
    g_scale[c] = a;
    g_shift[c] = beta[c] - mean * a;
    g_sum[c] = 0.f; g_sumsq[c] = 0.f;
}

// ---------------- launch ----------------
extern "C" void kernel_launch(void* const* d_in, const int* in_sizes, int n_in,
                              void* d_out, int out_size)
{
    const float* x     = (const float*)d_in[0];
    const float* adj   = (const float*)d_in[1];
    const float* w_g0  = (const float*)d_in[2];
    const float* b_g0  = (const float*)d_in[3];
    const float* w_g1  = (const float*)d_in[4];
    const float* b_g1  = (const float*)d_in[5];
    const float* w_g2  = (const float*)d_in[6];
    const float* b_g2  = (const float*)d_in[7];
    const float* gamma = (const float*)d_in[8];
    const float* beta  = (const float*)d_in[9];
    const float* w_r0  = (const float*)d_in[10];
    const float* b_r0  = (const float*)d_in[11];
    const float* w_fc  = (const float*)d_in[12];
    const float* b_fc  = (const float*)d_in[13];
    const float* w_fr  = (const float*)d_in[14];
    const float* b_fr  = (const float*)d_in[15];
    float* out = (float*)d_out;

    __half2 *pt16;
    float *ps, *ph, *pr;
    uint32_t *pwf;
    cudaGetSymbolAddress((void**)&pt16, g_t16);
    cudaGetSymbolAddress((void**)&ps, g_s);
    cudaGetSymbolAddress((void**)&ph, g_h);
    cudaGetSymbolAddress((void**)&pr, g_r);
    cudaGetSymbolAddress((void**)&pwf, g_wfrag);

    const int ROWB = ROWS / 128;               // 2000

    cudaFuncSetAttribute(gemm_in3,
                         cudaFuncAttributeMaxDynamicSharedMemorySize, IN3_SMEM_BYTES);

    // #0: degrees + ALL weight fragments (500 + 320 blocks)
    prep_deg_w<<<NN + WFRAG_WORDS/128, 128>>>(adj, w_g0, w_r0, w_fr, w_g1, w_g2, w_fc);

    // #1: t0 = fp16(x@w_g0+b0), r0 = x@w_r0+b_r0, out = x@w_fr+b_fr (x read once)
    gemm_in3<<<ROWB, 256, IN3_SMEM_BYTES>>>(x, b_g0, pt16, b_r0, pr, b_fr, out);

    // #2: fragment-major fp16 a_hat
    prep_fill_frag<<<512, 256>>>(adj);

    // #3: layer-0 SpMM-as-MMA  ← ncu capture slot
    spmm_mma<<<dim3(4, GG), 256>>>(pt16, ps);
    bn_finalize<<<1, HID>>>(gamma + 0 * HID, beta + 0 * HID);

    // layer 0 fused: h0 = relu(bn(s)) + r0; t1 = fp16(h0 @ w_g1 + b)
    gemm_tc<HID, HID, false, true, true, true><<<dim3(ROWB, 1), 256>>>(
        ps, pr, ph, b_g1, pt16, pwf + WOFF_G1);

    // layer 1
    spmm_mma<<<dim3(4, GG), 256>>>(pt16, ps);
    bn_finalize<<<1, HID>>>(gamma + 1 * HID, beta + 1 * HID);
    gemm_tc<HID, HID, false, true, true, true><<<dim3(ROWB, 1), 256>>>(
        ps, ph, ph, b_g2, pt16, pwf + WOFF_G2);

    // layer 2: h2 never materialized; out += h2 @ w_fc + b_fc
    spmm_mma<<<dim3(4, GG), 256>>>(pt16, ps);
    bn_finalize<<<1, HID>>>(gamma + 2 * HID, beta + 2 * HID);
    gemm_tc<HID, OUTF, true, true, false, false><<<dim3(ROWB, 2), 256>>>(
        ps, ph, nullptr, b_fc, out, pwf + WOFF_FC);
}

// round 17
// speedup vs baseline: 1.0533x; 1.0070x over previous
#include <cuda_runtime.h>
#include <cuda_fp16.h>
#include <cstdint>

#define GG 512            // B*T graphs
#define NN 500            // nodes
#define FIN 96
#define HID 64
#define OUTF 96
#define ROWS (GG*NN)      // 256000
#define BN_EPS 1e-5f

// weight-fragment table offsets (uint32 words)
#define WOFF_G0 0
#define WOFF_R0 6144
#define WOFF_FR 12288
#define WOFF_G1 24576
#define WOFF_G2 28672
#define WOFF_FC 32768
#define WFRAG_WORDS 40960

// ---------------- scratch (device globals; no allocation allowed) ----------------
__device__ __half2 g_t16[((long)ROWS + 16)*HID/2]; // GEMM output / SpMM input (fp16)
__device__ __half2 g_s16[(long)ROWS*HID/2];        // SpMM output (fp16)
__device__ uint32_t g_afrag[32*16*2*128];          // a_hat fragments, 512KB
__device__ uint32_t g_wfrag[WFRAG_WORDS];          // weight fragments, 160KB
__device__ float g_h[(long)ROWS*HID];    // layer activations (residual chain, fp32)
__device__ float g_r[(long)ROWS*HID];    // layer-0 residual (fp32)
__device__ float g_dinv[NN];
__device__ float g_sum[3*HID];           // per-layer BN partial sums
__device__ float g_sumsq[3*HID];

// ---------------- fp16 helpers ----------------
__device__ __forceinline__ uint32_t h2u(__half2 h) { return *(uint32_t*)&h; }

__device__ __forceinline__ void f16_split2(float a, float b, uint32_t& hi, uint32_t& lo) {
    __half2 h = __floats2half2_rn(a, b);
    float2 back = __half22float2(h);
    __half2 l = __floats2half2_rn(a - back.x, b - back.y);
    hi = h2u(h); lo = h2u(l);
}

__device__ __forceinline__ void mma_f16(float* c, const uint32_t* a, const uint32_t* b) {
    asm volatile(
        "mma.sync.aligned.m16n8k16.row.col.f32.f16.f16.f32 "
        "{%0,%1,%2,%3}, {%4,%5,%6,%7}, {%8,%9}, {%0,%1,%2,%3};\n"
        : "+f"(c[0]), "+f"(c[1]), "+f"(c[2]), "+f"(c[3])
        : "r"(a[0]), "r"(a[1]), "r"(a[2]), "r"(a[3]), "r"(b[0]), "r"(b[1]));
}

// ---------------- prep 1: degrees (blocks 0..499) + weight fragments (500+) ----
__global__ void prep_deg_w(const float* __restrict__ adj,
    const float* __restrict__ w_g0, const float* __restrict__ w_r0,
    const float* __restrict__ w_fr, const float* __restrict__ w_g1,
    const float* __restrict__ w_g2, const float* __restrict__ w_fc)
{
    int tid = threadIdx.x;
    if (blockIdx.x < NN) {
        int m = blockIdx.x;
        float sum = 0.f;
        for (int n = tid; n < NN; n += blockDim.x) sum += adj[m*NN + n];
        __shared__ float ssum[4];
        #pragma unroll
        for (int o = 16; o; o >>= 1) sum += __shfl_down_sync(0xFFFFFFFFu, sum, o);
        int w = tid >> 5;
        if ((tid & 31) == 0) ssum[w] = sum;
        __syncthreads();
        if (tid == 0)
            g_dinv[m] = rsqrtf(1.f + ssum[0] + ssum[1] + ssum[2] + ssum[3]);
        if (blockIdx.x == 0)
            for (int i = tid; i < 3*HID; i += 128) { g_sum[i] = 0.f; g_sumsq[i] = 0.f; }
        return;
    }
    int idx = (blockIdx.x - NN) * 128 + tid;     // 0..40959
    const float* W; int C, chunks, m;
    if (idx < WOFF_R0)      { W = w_g0; C=64; chunks=3; m = idx; }
    else if (idx < WOFF_FR) { W = w_r0; C=64; chunks=3; m = idx - WOFF_R0; }
    else if (idx < WOFF_G1) { W = w_fr; C=96; chunks=3; m = idx - WOFF_FR; }
    else if (idx < WOFF_G2) { W = w_g1; C=64; chunks=2; m = idx - WOFF_G1; }
    else if (idx < WOFF_FC) { W = w_g2; C=64; chunks=2; m = idx - WOFF_G2; }
    else                    { W = w_fc; C=96; chunks=2; m = idx - WOFF_FC; }
    int rem  = m & 2047;
    int cbch = m >> 11;
    int chunk = cbch % chunks;
    int colblk = cbch / chunks;
    int s    = (rem >> 10) & 1;
    int wn   = (rem >> 9) & 1;
    int lane = (rem >> 4) & 31;
    int j    = rem & 15;
    int reg  = j & 1;
    int nt   = (j >> 1) & 3;
    int col = colblk * 64 + wn * 32 + nt * 8 + (lane >> 2);
    int kpl = s * 8 + (lane & 3) + reg * 4;
    int k0  = chunk * 32 + 2 * kpl;
    float v0 = 0.f, v1 = 0.f;
    if (col < C) {
        v0 = W[(long)k0 * C + col];
        v1 = W[(long)(k0 + 1) * C + col];
    }
    uint32_t hi, lo;
    f16_split2(v0, v1, hi, lo);
    g_wfrag[idx] = (j >= 8) ? lo : hi;
}

// ---------------- prep 2: fragment-major fp16 a_hat ----------------
__device__ __forceinline__ float ahat_val(const float* adj, const float* dinv, int m, int n) {
    if (m >= NN || n >= NN) return 0.f;
    float dm = dinv[m];
    return (n == m) ? dm * dm : adj[m*NN + n] * dm * dinv[n];
}

__global__ __launch_bounds__(256) void prep_fill_frag(const float* __restrict__ adj) {
    __shared__ float sdinv[NN];
    int tid = threadIdx.x;
    for (int i = tid; i < NN; i += 256) sdinv[i] = g_dinv[i];
    __syncthreads();
    int idx = blockIdx.x * 256 + tid;           // 0 .. 131071
    int reg = idx & 3;
    int l   = (idx >> 2) & 31;
    int s   = (idx >> 7) & 1;
    int c   = (idx >> 8) & 15;
    int tau = idx >> 12;
    int g = l >> 2, t4 = l & 3;
    int row = tau * 16 + g + (reg & 1) * 8;
    int kp  = c * 16 + s * 8 + t4 + (reg >> 1) * 4;
    __half2 v = __floats2half2_rn(ahat_val(adj, sdinv, row, 2*kp),
                                  ahat_val(adj, sdinv, row, 2*kp + 1));
    g_afrag[idx] = *(uint32_t*)&v;
}

// ---------------- SpMM as batched dense MMA + fused BN stats ----------------
__global__ __launch_bounds__(256) void spmm_mma(
    const __half2* __restrict__ T2, __half2* __restrict__ S16,
    float* __restrict__ gsum, float* __restrict__ gsumsq)
{
    __shared__ uint32_t Bs[2][16][72];
    __shared__ float ssum[8][32], ssq[8][32];

    const int tid = threadIdx.x;
    const int wid = tid >> 5;
    const int lane = tid & 31;
    const int g  = lane >> 2;
    const int t4 = lane & 3;
    const int warp_m = wid >> 1;
    const int warp_n = wid & 1;

    const int gph = blockIdx.y;
    const int rt = blockIdx.x;
    const __half* Tg = (const __half*)T2 + (long)gph * NN * HID;
    __half2* Sg = S16 + (long)gph * NN * (HID/2);

    const int bkp = tid >> 3;
    const int bcq = tid & 7;

    auto stageB = [&](int c, uint32_t (*B)[72]) {
        long k = c * 32 + 2 * bkp;
        uint4 lo = *(const uint4*)(Tg + k * HID + bcq * 8);
        uint4 hi = *(const uint4*)(Tg + (k + 1) * HID + bcq * 8);
        const __half2* l2 = (const __half2*)&lo;
        const __half2* h2 = (const __half2*)&hi;
        uint32_t w[8];
        #pragma unroll
        for (int j = 0; j < 4; j++) {
            w[2*j]   = h2u(__lows2half2(l2[j], h2[j]));
            w[2*j+1] = h2u(__highs2half2(l2[j], h2[j]));
        }
        *(uint4*)&B[bkp][bcq*8]     = make_uint4(w[0], w[1], w[2], w[3]);
        *(uint4*)&B[bkp][bcq*8 + 4] = make_uint4(w[4], w[5], w[6], w[7]);
    };

    float acc[2][4][4];
    #pragma unroll
    for (int mt = 0; mt < 2; mt++)
        #pragma unroll
        for (int nt = 0; nt < 4; nt++)
            #pragma unroll
            for (int q = 0; q < 4; q++) acc[mt][nt][q] = 0.f;

    if (tid < 128) stageB(0, Bs[0]);
    __syncthreads();

    for (int c = 0; c < 16; c++) {
        int cur = c & 1;
        if (c < 15 && tid < 128) stageB(c + 1, Bs[cur ^ 1]);

        #pragma unroll
        for (int s = 0; s < 2; s++) {
            uint32_t a[2][4], b[4][2];
            #pragma unroll
            for (int mt = 0; mt < 2; mt++) {
                int tau = rt * 8 + warp_m * 2 + mt;
                const uint4 v = *(const uint4*)(g_afrag + (((tau*16 + c)*2 + s)*128 + lane*4));
                a[mt][0] = v.x; a[mt][1] = v.y; a[mt][2] = v.z; a[mt][3] = v.w;
            }
            #pragma unroll
            for (int nt = 0; nt < 4; nt++) {
                int nb = warp_n * 32 + nt * 8 + g;
                int kr = s * 8 + t4;
                b[nt][0] = Bs[cur][kr][nb];    b[nt][1] = Bs[cur][kr+4][nb];
            }
            #pragma unroll
            for (int mt = 0; mt < 2; mt++)
                #pragma unroll
                for (int nt = 0; nt < 4; nt++)
                    mma_f16(acc[mt][nt], a[mt], b[nt]);
        }
        __syncthreads();
    }

    // --- epilogue: store S as fp16 (guard row < 500) ---
    const int row0 = rt * 128;
    #pragma unroll
    for (int mt = 0; mt < 2; mt++) {
        int rowa = row0 + warp_m * 32 + mt * 16 + g;
        int rowb = rowa + 8;
        #pragma unroll
        for (int nt = 0; nt < 4; nt++) {
            int col = warp_n * 32 + nt * 8 + 2 * t4;   // even
            if (rowa < NN)
                Sg[rowa * (HID/2) + (col >> 1)] = __floats2half2_rn(acc[mt][nt][0], acc[mt][nt][1]);
            if (rowb < NN)
                Sg[rowb * (HID/2) + (col >> 1)] = __floats2half2_rn(acc[mt][nt][2], acc[mt][nt][3]);
        }
    }

    // --- BN stats from exact fp32 accumulators ---
    float ls[8], lq[8];
    #pragma unroll
    for (int nt = 0; nt < 4; nt++)
        #pragma unroll
        for (int b = 0; b < 2; b++) {
            float v0 = acc[0][nt][b], v1 = acc[0][nt][b+2];
            float v2 = acc[1][nt][b], v3 = acc[1][nt][b+2];
            ls[nt*2+b] = v0 + v1 + v2 + v3;
            lq[nt*2+b] = v0*v0 + v1*v1 + v2*v2 + v3*v3;
        }
    #pragma unroll
    for (int i = 0; i < 8; i++) {
        #pragma unroll
        for (int off = 4; off <= 16; off <<= 1) {
            ls[i] += __shfl_xor_sync(0xFFFFFFFFu, ls[i], off);
            lq[i] += __shfl_xor_sync(0xFFFFFFFFu, lq[i], off);
        }
    }
    if (lane < 4) {
        #pragma unroll
        for (int nt = 0; nt < 4; nt++)
            #pragma unroll
            for (int b = 0; b < 2; b++) {
                ssum[wid][nt*8 + 2*lane + b] = ls[nt*2+b];
                ssq [wid][nt*8 + 2*lane + b] = lq[nt*2+b];
            }
    }
    __syncthreads();
    if (tid < 128) {
        int col = tid & 63;
        int wn = col >> 5, lc = col & 31;
        bool isq = tid >= 64;
        float t = 0.f;
        #pragma unroll
        for (int w = 0; w < 4; w++) {
            int wd = w * 2 + wn;
            t += isq ? ssq[wd][lc] : ssum[wd][lc];
        }
        atomicAdd(isq ? &gsumsq[col] : &gsum[col], t);
    }
}

// ---------------- fused BN+GEMM: A = relu(bn(S16))+R, B from wfrag, K=64 ---------
template<int C, bool ACCUM, bool WRITE_H, bool OUT_HALF>
__global__ __launch_bounds__(256) void gemm_tc(
    const __half2* __restrict__ S16, const float* __restrict__ R, float* __restrict__ Hout,
    const float* __restrict__ bias, void* __restrict__ Cout,
    const uint32_t* __restrict__ wf,
    const float* __restrict__ gamma, const float* __restrict__ beta,
    const float* __restrict__ gsum, const float* __restrict__ gsumsq)
{
    __shared__ uint32_t AsH[128][36], AsL[128][36];
    __shared__ float s_scale[HID], s_shift[HID];

    const int tid = threadIdx.x;
    const int wid = tid >> 5;
    const int lane = tid & 31;
    const int g  = lane >> 2;
    const int t4 = lane & 3;
    const int warp_m = wid >> 1;
    const int warp_n = wid & 1;

    const long row0 = (long)blockIdx.x * 128;
    const int colblk = blockIdx.y;
    const int col0 = colblk * 64;

    if (tid < HID) {
        const float inv = 1.f / (float)ROWS;
        float s = gsum[tid], q = gsumsq[tid];
        float mean = s * inv;
        float var = q * inv - mean * mean;
        float a = rsqrtf(var + BN_EPS) * gamma[tid];
        s_scale[tid] = a;
        s_shift[tid] = beta[tid] - mean * a;
    }
    __syncthreads();

    // stage + split FULL A tile: 128 rows x 64 chans (fp16 S + fp32 R)
    #pragma unroll
    for (int i = 0; i < 8; i++) {
        int idx = tid + i * 256;        // 2048 tasks of 4 chans
        int r = idx >> 4;
        int q = idx & 15;
        long off = (row0 + r) * HID + q * 4;
        uint2 sv = *(const uint2*)((const __half*)S16 + off);
        float2 f01 = __half22float2(*(__half2*)&sv.x);
        float2 f23 = __half22float2(*(__half2*)&sv.y);
        float4 rv = *(const float4*)(R + off);
        int kc = q * 4;
        float4 v;
        v.x = fmaxf(f01.x * s_scale[kc+0] + s_shift[kc+0], 0.f) + rv.x;
        v.y = fmaxf(f01.y * s_scale[kc+1] + s_shift[kc+1], 0.f) + rv.y;
        v.z = fmaxf(f23.x * s_scale[kc+2] + s_shift[kc+2], 0.f) + rv.z;
        v.w = fmaxf(f23.y * s_scale[kc+3] + s_shift[kc+3], 0.f) + rv.w;
        if (WRITE_H) *(float4*)(Hout + off) = v;
        uint32_t h01, l01, h23, l23;
        f16_split2(v.x, v.y, h01, l01);
        f16_split2(v.z, v.w, h23, l23);
        *(uint2*)&AsH[r][q*2] = make_uint2(h01, h23);
        *(uint2*)&AsL[r][q*2] = make_uint2(l01, l23);
    }
    __syncthreads();

    float acc[2][4][4];
    #pragma unroll
    for (int mt = 0; mt < 2; mt++)
        #pragma unroll
        for (int nt = 0; nt < 4; nt++)
            #pragma unroll
            for (int q = 0; q < 4; q++) acc[mt][nt][q] = 0.f;

    #pragma unroll
    for (int chunk = 0; chunk < 2; chunk++) {
        #pragma unroll
        for (int s = 0; s < 2; s++) {
            const uint32_t* bp = wf +
                ((((colblk * 2 + chunk) * 2 + s) * 2 + warp_n) * 32 + lane) * 16;
            uint4 bh0 = *(const uint4*)(bp);
            uint4 bh1 = *(const uint4*)(bp + 4);
            uint4 bl0 = *(const uint4*)(bp + 8);
            uint4 bl1 = *(const uint4*)(bp + 12);
            uint32_t bh[4][2] = {{bh0.x,bh0.y},{bh0.z,bh0.w},{bh1.x,bh1.y},{bh1.z,bh1.w}};
            uint32_t bl[4][2] = {{bl0.x,bl0.y},{bl0.z,bl0.w},{bl1.x,bl1.y},{bl1.z,bl1.w}};

            uint32_t ah[2][4], al[2][4];
            #pragma unroll
            for (int mt = 0; mt < 2; mt++) {
                int r = warp_m * 32 + mt * 16 + g;
                int kc = chunk * 16 + s * 8 + t4;
                ah[mt][0] = AsH[r][kc];     al[mt][0] = AsL[r][kc];
                ah[mt][1] = AsH[r+8][kc];   al[mt][1] = AsL[r+8][kc];
                ah[mt][2] = AsH[r][kc+4];   al[mt][2] = AsL[r][kc+4];
                ah[mt][3] = AsH[r+8][kc+4]; al[mt][3] = AsL[r+8][kc+4];
            }
            #pragma unroll
            for (int mt = 0; mt < 2; mt++)
                #pragma unroll
                for (int nt = 0; nt < 4; nt++) {
                    mma_f16(acc[mt][nt], ah[mt], bh[nt]);
                    mma_f16(acc[mt][nt], ah[mt], bl[nt]);
                    mma_f16(acc[mt][nt], al[mt], bh[nt]);
                }
        }
    }

    #pragma unroll
    for (int mt = 0; mt < 2; mt++) {
        long rowa = row0 + warp_m * 32 + mt * 16 + g;
        long rowb = rowa + 8;
        #pragma unroll
        for (int nt = 0; nt < 4; nt++) {
            int col = col0 + warp_n * 32 + nt * 8 + 2 * t4;
            if ((C & 63) == 0 || col < C) {
                float bx = bias[col];
                float by = bias[col + 1];
                float2 v0 = make_float2(acc[mt][nt][0] + bx, acc[mt][nt][1] + by);
                float2 v1 = make_float2(acc[mt][nt][2] + bx, acc[mt][nt][3] + by);
                if (OUT_HALF) {
                    __half2* o = (__half2*)Cout;
                    o[(rowa * C + col) >> 1] = __floats2half2_rn(v0.x, v0.y);
                    o[(rowb * C + col) >> 1] = __floats2half2_rn(v1.x, v1.y);
                } else {
                    float* d0 = (float*)Cout + rowa * C + col;
                    float* d1 = (float*)Cout + rowb * C + col;
                    if (ACCUM) {
                        float2 o0 = *(const float2*)d0;
                        float2 o1 = *(const float2*)d1;
                        v0.x += o0.x; v0.y += o0.y;
                        v1.x += o1.x; v1.y += o1.y;
                    }
                    *(float2*)d0 = v0;
                    *(float2*)d1 = v1;
                }
            }
        }
    }
}

// ---------------- fused input GEMM (x read ONCE; B from wfrag; 1 sync) -------
#define IN3_SMEM_WORDS (2 * 128 * 52)
#define IN3_SMEM_BYTES (IN3_SMEM_WORDS * 4)

__global__ __launch_bounds__(256) void gemm_in3(
    const float* __restrict__ A,
    const float* __restrict__ b_g0, __half2* __restrict__ T,
    const float* __restrict__ b_r0, float* __restrict__ Rr,
    const float* __restrict__ b_fr, float* __restrict__ Out)
{
    extern __shared__ uint32_t dsm[];
    uint32_t (*AsH)[52] = (uint32_t(*)[52])(dsm);
    uint32_t (*AsL)[52] = (uint32_t(*)[52])(dsm + 128*52);

    const int tid = threadIdx.x;
    const int wid = tid >> 5;
    const int lane = tid & 31;
    const int g  = lane >> 2;
    const int t4 = lane & 3;
    const int warp_m = wid >> 1;
    const int warp_n = wid & 1;
    const long row0 = (long)blockIdx.x * 128;

    #pragma unroll
    for (int i = 0; i < 12; i++) {
        int idx = tid + i * 256;
        int r = idx / 24;
        int q = idx % 24;
        float4 v = *(const float4*)(A + (row0 + r) * FIN + q * 4);
        uint32_t h01, l01, h23, l23;
        f16_split2(v.x, v.y, h01, l01);
        f16_split2(v.z, v.w, h23, l23);
        *(uint2*)&AsH[r][q*2] = make_uint2(h01, h23);
        *(uint2*)&AsL[r][q*2] = make_uint2(l01, l23);
    }
    __syncthreads();

    const int woffs[4]  = {WOFF_G0, WOFF_R0, WOFF_FR, WOFF_FR};
    const int cblks[4]  = {0, 0, 0, 1};
    const float* biass[4] = {b_g0, b_r0, b_fr, b_fr};

    #pragma unroll 1
    for (int phase = 0; phase < 4; phase++) {
        const float* bia = biass[phase];
        const int col0 = (phase == 3) ? 64 : 0;
        const int C = (phase >= 2) ? OUTF : HID;
        const uint32_t* wf = g_wfrag + woffs[phase];
        const int cb = cblks[phase];

        float acc[2][4][4];
        #pragma unroll
        for (int mt = 0; mt < 2; mt++)
            #pragma unroll
            for (int nt = 0; nt < 4; nt++)
                #pragma unroll
                for (int q = 0; q < 4; q++) acc[mt][nt][q] = 0.f;

        #pragma unroll
        for (int chunk = 0; chunk < 3; chunk++) {
            #pragma unroll
            for (int s = 0; s < 2; s++) {
                const uint32_t* bp = wf +
                    ((((cb * 3 + chunk) * 2 + s) * 2 + warp_n) * 32 + lane) * 16;
                uint4 bh0 = *(const uint4*)(bp);
                uint4 bh1 = *(const uint4*)(bp + 4);
                uint4 bl0 = *(const uint4*)(bp + 8);
                uint4 bl1 = *(const uint4*)(bp + 12);
                uint32_t bh[4][2] = {{bh0.x,bh0.y},{bh0.z,bh0.w},{bh1.x,bh1.y},{bh1.z,bh1.w}};
                uint32_t bl[4][2] = {{bl0.x,bl0.y},{bl0.z,bl0.w},{bl1.x,bl1.y},{bl1.z,bl1.w}};

                uint32_t ah[2][4], al[2][4];
                #pragma unroll
                for (int mt = 0; mt < 2; mt++) {
                    int r = warp_m * 32 + mt * 16 + g;
                    int kc = chunk * 16 + s * 8 + t4;
                    ah[mt][0] = AsH[r][kc];     al[mt][0] = AsL[r][kc];
                    ah[mt][1] = AsH[r+8][kc];   al[mt][1] = AsL[r+8][kc];
                    ah[mt][2] = AsH[r][kc+4];   al[mt][2] = AsL[r][kc+4];
                    ah[mt][3] = AsH[r+8][kc+4]; al[mt][3] = AsL[r+8][kc+4];
                }
                #pragma unroll
                for (int mt = 0; mt < 2; mt++)
                    #pragma unroll
                    for (int nt = 0; nt < 4; nt++) {
                        mma_f16(acc[mt][nt], ah[mt], bh[nt]);
                        mma_f16(acc[mt][nt], ah[mt], bl[nt]);
                        mma_f16(acc[mt][nt], al[mt], bh[nt]);
                    }
            }
        }

        #pragma unroll
        for (int mt = 0; mt < 2; mt++) {
            long rowa = row0 + warp_m * 32 + mt * 16 + g;
            long rowb = rowa + 8;
            #pragma unroll
            for (int nt = 0; nt < 4; nt++) {
                int col = col0 + warp_n * 32 + nt * 8 + 2 * t4;
                if (col < C) {
                    float bx = bia[col];
                    float by = bia[col + 1];
                    float2 v0 = make_float2(acc[mt][nt][0] + bx, acc[mt][nt][1] + by);
                    float2 v1 = make_float2(acc[mt][nt][2] + bx, acc[mt][nt][3] + by);
                    if (phase == 0) {
                        T[(rowa * HID + col) >> 1] = __floats2half2_rn(v0.x, v0.y);
                        T[(rowb * HID + col) >> 1] = __floats2half2_rn(v1.x, v1.y);
                    } else if (phase == 1) {
                        *(float2*)(Rr + rowa * HID + col) = v0;
                        *(float2*)(Rr + rowb * HID + col) = v1;
                    } else {
                        *(float2*)(Out + rowa * OUTF + col) = v0;
                        *(float2*)(Out + rowb * OUTF + col) = v1;
                    }
                }
            }
        }
    }
}

// ---------------- launch ----------------
extern "C" void kernel_launch(void* const* d_in, const int* in_sizes, int n_in,
                              void* d_out, int out_size)
{
    const float* x     = (const float*)d_in[0];
    const float* adj   = (const float*)d_in[1];
    const float* w_g0  = (const float*)d_in[2];
    const float* b_g0  = (const float*)d_in[3];
    const float* w_g1  = (const float*)d_in[4];
    const float* b_g1  = (const float*)d_in[5];
    const float* w_g2  = (const float*)d_in[6];
    const float* b_g2  = (const float*)d_in[7];
    const float* gamma = (const float*)d_in[8];
    const float* beta  = (const float*)d_in[9];
    const float* w_r0  = (const float*)d_in[10];
    const float* b_r0  = (const float*)d_in[11];
    const float* w_fc  = (const float*)d_in[12];
    const float* b_fc  = (const float*)d_in[13];
    const float* w_fr  = (const float*)d_in[14];
    const float* b_fr  = (const float*)d_in[15];
    float* out = (float*)d_out;

    __half2 *pt16, *ps16;
    float *ph, *pr, *psum, *psq;
    uint32_t *pwf;
    cudaGetSymbolAddress((void**)&pt16, g_t16);
    cudaGetSymbolAddress((void**)&ps16, g_s16);
    cudaGetSymbolAddress((void**)&ph, g_h);
    cudaGetSymbolAddress((void**)&pr, g_r);
    cudaGetSymbolAddress((void**)&pwf, g_wfrag);
    cudaGetSymbolAddress((void**)&psum, g_sum);
    cudaGetSymbolAddress((void**)&psq, g_sumsq);

    const int ROWB = ROWS / 128;               // 2000

    cudaFuncSetAttribute(gemm_in3,
                         cudaFuncAttributeMaxDynamicSharedMemorySize, IN3_SMEM_BYTES);

    // #0: degrees + BN-stat zeroing + ALL weight fragments
    prep_deg_w<<<NN + WFRAG_WORDS/128, 128>>>(adj, w_g0, w_r0, w_fr, w_g1, w_g2, w_fc);

    // #1: t0 = fp16(x@w_g0+b0), r0 = x@w_r0+b_r0, out = x@w_fr+b_fr (x read once)
    gemm_in3<<<ROWB, 256, IN3_SMEM_BYTES>>>(x, b_g0, pt16, b_r0, pr, b_fr, out);

    // #2: fragment-major fp16 a_hat
    prep_fill_frag<<<512, 256>>>(adj);

    // #3: layer-0 SpMM-as-MMA  ← ncu capture slot
    spmm_mma<<<dim3(4, GG), 256>>>(pt16, ps16, psum, psq);

    // layer 0 fused: bn0 + relu + r0; t1 = fp16(h0 @ w_g1 + b); h0 -> g_h
    gemm_tc<HID, false, true, true><<<dim3(ROWB, 1), 256>>>(
        ps16, pr, ph, b_g1, pt16, pwf + WOFF_G1, gamma, beta, psum, psq);

    // layer 1
    spmm_mma<<<dim3(4, GG), 256>>>(pt16, ps16, psum + HID, psq + HID);
    gemm_tc<HID, false, true, true><<<dim3(ROWB, 1), 256>>>(
        ps16, ph, ph, b_g2, pt16, pwf + WOFF_G2, gamma + HID, beta + HID, psum + HID, psq + HID);

    // layer 2: h2 never materialized; out += h2 @ w_fc + b_fc
    spmm_mma<<<dim3(4, GG), 256>>>(pt16, ps16, psum + 2*HID, psq + 2*HID);
    gemm_tc<OUTF, true, false, false><<<dim3(ROWB, 2), 256>>>(
        ps16, ph, nullptr, b_fc, out, pwf + WOFF_FC, gamma + 2*HID, beta + 2*HID,
        psum + 2*HID, psq + 2*HID);
}